// round 1
// baseline (speedup 1.0000x reference)
#include <cuda_runtime.h>

#define NN 100000
#define NE 1000000
#define DI 128
#define DO 64

// ---------------- scratch (device globals: no runtime allocation) ----------
__device__ float g_h0[NN * DO];
__device__ float g_u[NN * DO];
__device__ float g_acc[NN * DO];
__device__ float g_h[NN * DO];
__device__ float g_A[NN * DO];
__device__ float g_B[NN * DO];
__device__ int   g_deg[NN];
__device__ float g_e[NN];
__device__ float g_q[NN];
__device__ float g_Qs[NN];
__device__ float g_dinv[NN];
__device__ float g_pmax[256];
__device__ float g_pz[256];
__device__ float g_pw[256];
__device__ float g_scal[4];   // 0:m  1:1/Z  2:logZ  3:H

// ---------------- helpers ---------------------------------------------------
__device__ __forceinline__ void red_add_v4(float* addr, float a, float b, float c, float d) {
    asm volatile("red.global.add.v4.f32 [%0], {%1, %2, %3, %4};"
                 :: "l"(addr), "f"(a), "f"(b), "f"(c), "f"(d) : "memory");
}
__device__ __forceinline__ void red_add_f32(float* addr, float v) {
    asm volatile("red.global.add.f32 [%0], %1;" :: "l"(addr), "f"(v) : "memory");
}

// ---------------- kernels ---------------------------------------------------
__global__ __launch_bounds__(256) void k_zero() {
    int idx = blockIdx.x * 256 + threadIdx.x;
    if (idx < NN * DO) {
        g_acc[idx] = 0.f;
        g_A[idx]   = 0.f;
        g_B[idx]   = 0.f;
    }
    if (idx < NN) {
        g_deg[idx] = 0;
        g_e[idx]   = 0.f;
        g_Qs[idx]  = 0.f;
    }
}

__global__ __launch_bounds__(256) void k_deg(const int* __restrict__ ei) {
    int t = blockIdx.x * 256 + threadIdx.x;
    if (t < NE) atomicAdd(&g_deg[ei[NE + t]], 1);
}

// h0 = x @ W ; 128 rows/block, each thread: 4 rows x 8 cols
__global__ __launch_bounds__(256) void k_gemm(const float* __restrict__ x,
                                              const float* __restrict__ W) {
    __shared__ float Ws[DI * DO];     // 32 KB
    __shared__ float xs[128 * 17];    // 128 rows x 16 k, padded
    int t = threadIdx.x;
    int row0 = blockIdx.x * 128;
    for (int i = t; i < DI * DO; i += 256) Ws[i] = W[i];

    int cg = t & 7;          // col group: cols cg*8 .. cg*8+7
    int rt = t >> 3;         // 0..31 -> rows rt*4 .. rt*4+3
    float acc[4][8];
#pragma unroll
    for (int i = 0; i < 4; i++)
#pragma unroll
        for (int j = 0; j < 8; j++) acc[i][j] = 0.f;

    for (int kc = 0; kc < 8; kc++) {
        __syncthreads();
        for (int i = t; i < 128 * 16; i += 256) {
            int r = i >> 4, k = i & 15;
            int gr = row0 + r;
            xs[r * 17 + k] = (gr < NN) ? x[gr * DI + kc * 16 + k] : 0.f;
        }
        __syncthreads();
#pragma unroll
        for (int k = 0; k < 16; k++) {
            float4 w0 = *(const float4*)(Ws + (kc * 16 + k) * DO + cg * 8);
            float4 w1 = *(const float4*)(Ws + (kc * 16 + k) * DO + cg * 8 + 4);
#pragma unroll
            for (int i = 0; i < 4; i++) {
                float xv = xs[(rt * 4 + i) * 17 + k];
                acc[i][0] += xv * w0.x; acc[i][1] += xv * w0.y;
                acc[i][2] += xv * w0.z; acc[i][3] += xv * w0.w;
                acc[i][4] += xv * w1.x; acc[i][5] += xv * w1.y;
                acc[i][6] += xv * w1.z; acc[i][7] += xv * w1.w;
            }
        }
    }
#pragma unroll
    for (int i = 0; i < 4; i++) {
        int gr = row0 + rt * 4 + i;
        if (gr < NN) {
            float4* p = (float4*)(g_h0 + gr * DO + cg * 8);
            p[0] = make_float4(acc[i][0], acc[i][1], acc[i][2], acc[i][3]);
            p[1] = make_float4(acc[i][4], acc[i][5], acc[i][6], acc[i][7]);
        }
    }
}

__global__ __launch_bounds__(256) void k_dinv() {
    int v = blockIdx.x * 256 + threadIdx.x;
    if (v < NN) g_dinv[v] = rsqrtf((float)(g_deg[v] + 1));
}

__global__ __launch_bounds__(256) void k_u() {
    int idx = blockIdx.x * 256 + threadIdx.x;
    if (idx < NN * DO) g_u[idx] = g_h0[idx] * g_dinv[idx >> 6];
}

// acc[dst] += u[src]   (16 threads/edge, float4 lanes)
__global__ __launch_bounds__(256) void k_scat1(const int* __restrict__ ei) {
    int t = blockIdx.x * 256 + threadIdx.x;
    int e = t >> 4, q = t & 15;
    if (e >= NE) return;
    int s = ei[e], d = ei[NE + e];
    float4 us = *(const float4*)(g_u + s * DO + q * 4);
    red_add_v4(g_acc + d * DO + q * 4, us.x, us.y, us.z, us.w);
}

__global__ __launch_bounds__(256) void k_h(const float* __restrict__ b) {
    int idx = blockIdx.x * 256 + threadIdx.x;
    if (idx >= NN * DO) return;
    int v = idx >> 6, c = idx & 63;
    float dv = g_dinv[v];
    g_h[idx] = dv * g_acc[idx] + g_h0[idx] * dv * dv + b[c];
}

// A[dst] += h[src];  e[dst] += ||h_dst - h_src||^2
__global__ __launch_bounds__(256) void k_edge2(const int* __restrict__ ei) {
    int t = blockIdx.x * 256 + threadIdx.x;
    int e = t >> 4, q = t & 15;
    if (e >= NE) return;
    int s = ei[e], d = ei[NE + e];
    float4 hs = *(const float4*)(g_h + s * DO + q * 4);
    float4 hd = *(const float4*)(g_h + d * DO + q * 4);
    float dx = hd.x - hs.x, dy = hd.y - hs.y, dz = hd.z - hs.z, dw = hd.w - hs.w;
    float p = dx * dx + dy * dy + dz * dz + dw * dw;
    red_add_v4(g_A + d * DO + q * 4, hs.x, hs.y, hs.z, hs.w);
#pragma unroll
    for (int off = 8; off; off >>= 1)
        p += __shfl_down_sync(0xffffffffu, p, off, 16);
    if (q == 0) red_add_f32(g_e + d, p);
}

__global__ __launch_bounds__(256) void k_max(const float* __restrict__ temp) {
    float tmp = temp[0];
    float m = -1e30f;
    for (int i = blockIdx.x * 256 + threadIdx.x; i < NN; i += gridDim.x * 256)
        m = fmaxf(m, -g_e[i] / tmp);
    __shared__ float sm[256];
    sm[threadIdx.x] = m; __syncthreads();
    for (int o = 128; o; o >>= 1) {
        if (threadIdx.x < o) sm[threadIdx.x] = fmaxf(sm[threadIdx.x], sm[threadIdx.x + o]);
        __syncthreads();
    }
    if (threadIdx.x == 0) g_pmax[blockIdx.x] = sm[0];
}

__global__ __launch_bounds__(256) void k_maxfin() {
    __shared__ float sm[256];
    sm[threadIdx.x] = g_pmax[threadIdx.x];
    __syncthreads();
    for (int o = 128; o; o >>= 1) {
        if (threadIdx.x < o) sm[threadIdx.x] = fmaxf(sm[threadIdx.x], sm[threadIdx.x + o]);
        __syncthreads();
    }
    if (threadIdx.x == 0) g_scal[0] = sm[0];
}

__global__ __launch_bounds__(256) void k_sum(const float* __restrict__ temp) {
    float tmp = temp[0];
    float m = g_scal[0];
    float z = 0.f, w = 0.f;
    for (int i = blockIdx.x * 256 + threadIdx.x; i < NN; i += gridDim.x * 256) {
        float s = -g_e[i] / tmp - m;
        float ez = expf(s);
        z += ez; w += ez * s;
    }
    __shared__ float sz[256], sw[256];
    sz[threadIdx.x] = z; sw[threadIdx.x] = w; __syncthreads();
    for (int o = 128; o; o >>= 1) {
        if (threadIdx.x < o) {
            sz[threadIdx.x] += sz[threadIdx.x + o];
            sw[threadIdx.x] += sw[threadIdx.x + o];
        }
        __syncthreads();
    }
    if (threadIdx.x == 0) { g_pz[blockIdx.x] = sz[0]; g_pw[blockIdx.x] = sw[0]; }
}

__global__ __launch_bounds__(256) void k_sumfin() {
    __shared__ float sz[256], sw[256];
    sz[threadIdx.x] = g_pz[threadIdx.x];
    sw[threadIdx.x] = g_pw[threadIdx.x];
    __syncthreads();
    for (int o = 128; o; o >>= 1) {
        if (threadIdx.x < o) {
            sz[threadIdx.x] += sz[threadIdx.x + o];
            sw[threadIdx.x] += sw[threadIdx.x + o];
        }
        __syncthreads();
    }
    if (threadIdx.x == 0) {
        float Z = sz[0], Wm = sw[0];
        float logZ = logf(Z);
        g_scal[1] = 1.f / Z;
        g_scal[2] = logZ;
        g_scal[3] = logZ - Wm / Z;   // H
    }
}

__global__ __launch_bounds__(256) void k_q(const float* __restrict__ temp) {
    int v = blockIdx.x * 256 + threadIdx.x;
    if (v >= NN) return;
    float tmp = temp[0];
    float s = -g_e[v] / tmp - g_scal[0];        // s - m
    float lp = s - g_scal[2];                   // logp
    g_q[v] = expf(s) * g_scal[1] * (lp + g_scal[3]);
}

// B[src] += q[dst] * h[dst];  Qs[src] += q[dst]
__global__ __launch_bounds__(256) void k_edge3(const int* __restrict__ ei) {
    int t = blockIdx.x * 256 + threadIdx.x;
    int e = t >> 4, q = t & 15;
    if (e >= NE) return;
    int s = ei[e], d = ei[NE + e];
    float qd = g_q[d];
    float4 hd = *(const float4*)(g_h + d * DO + q * 4);
    red_add_v4(g_B + s * DO + q * 4, qd * hd.x, qd * hd.y, qd * hd.z, qd * hd.w);
    if (q == 0) red_add_f32(g_Qs + s, qd);
}

__global__ __launch_bounds__(256) void k_final(const float* __restrict__ wgt,
                                               float* __restrict__ out) {
    int idx = blockIdx.x * 256 + threadIdx.x;
    if (idx >= NN * DO) return;
    int v = idx >> 6;
    float h = g_h[idx];
    float w2 = 2.f * wgt[0];
    float g = g_q[v] * ((float)g_deg[v] * h - g_A[idx]) + g_Qs[v] * h - g_B[idx];
    out[idx] = h + w2 * g;
}

// ---------------- launch ----------------------------------------------------
extern "C" void kernel_launch(void* const* d_in, const int* in_sizes, int n_in,
                              void* d_out, int out_size) {
    const float* x    = (const float*)d_in[0];
    const int*   ei   = (const int*)d_in[1];
    const float* wgt  = (const float*)d_in[2];
    const float* temp = (const float*)d_in[3];
    const float* W    = (const float*)d_in[4];
    const float* b    = (const float*)d_in[5];
    float* out = (float*)d_out;

    const int NB_NODE = (NN * DO + 255) / 256;       // elementwise over N*64
    const int NB_E16  = (NE * 16) / 256;             // 16 threads / edge
    const int NB_E    = (NE + 255) / 256;
    const int NB_N    = (NN + 255) / 256;

    k_zero<<<NB_NODE, 256>>>();
    k_deg<<<NB_E, 256>>>(ei);
    k_gemm<<<(NN + 127) / 128, 256>>>(x, W);
    k_dinv<<<NB_N, 256>>>();
    k_u<<<NB_NODE, 256>>>();
    k_scat1<<<NB_E16, 256>>>(ei);
    k_h<<<NB_NODE, 256>>>(b);
    k_edge2<<<NB_E16, 256>>>(ei);
    k_max<<<256, 256>>>(temp);
    k_maxfin<<<1, 256>>>();
    k_sum<<<256, 256>>>(temp);
    k_sumfin<<<1, 256>>>();
    k_q<<<NB_N, 256>>>(temp);
    k_edge3<<<NB_E16, 256>>>(ei);
    k_final<<<NB_NODE, 256>>>(wgt, out);
}

// round 2
// speedup vs baseline: 1.0419x; 1.0419x over previous
#include <cuda_runtime.h>

#define NN 100000
#define NE 1000000
#define DI 128
#define DO 64

// ---------------- scratch (device globals) ----------------------------------
__device__ float g_h0[NN * DO];
__device__ float g_acc[NN * DO];
__device__ float g_h[NN * DO];
__device__ float g_A[NN * DO];
__device__ float g_B[NN * DO];
__device__ int   g_deg[NN];
__device__ float g_e[NN];     // accumulates sum of ||h_src||^2, then full e
__device__ float g_nh[NN];    // ||h_v||^2
__device__ float g_q[NN];
__device__ float g_Qs[NN];
__device__ float g_dinv[NN];
__device__ float g_pmax[256];
__device__ float g_pz[256];
__device__ float g_pw[256];
__device__ float g_scal[4];   // 0:m  1:1/Z  2:logZ  3:H

// ---------------- helpers ---------------------------------------------------
__device__ __forceinline__ void red_add_v4(float* addr, float a, float b, float c, float d) {
    asm volatile("red.global.add.v4.f32 [%0], {%1, %2, %3, %4};"
                 :: "l"(addr), "f"(a), "f"(b), "f"(c), "f"(d) : "memory");
}
__device__ __forceinline__ void red_add_f32(float* addr, float v) {
    asm volatile("red.global.add.f32 [%0], %1;" :: "l"(addr), "f"(v) : "memory");
}

// ---------------- kernels ---------------------------------------------------
__global__ __launch_bounds__(256) void k_zero() {
    int idx = blockIdx.x * 256 + threadIdx.x;
    if (idx < NN * DO) {
        g_acc[idx] = 0.f;
        g_A[idx]   = 0.f;
        g_B[idx]   = 0.f;
    }
    if (idx < NN) {
        g_deg[idx] = 0;
        g_e[idx]   = 0.f;
        g_Qs[idx]  = 0.f;
    }
}

__global__ __launch_bounds__(256) void k_deg(const int* __restrict__ ei) {
    int t = blockIdx.x * 256 + threadIdx.x;
    if (t < NE) atomicAdd(&g_deg[ei[NE + t]], 1);
}

// h0 = x @ W ; block: 128 rows x 64 cols, 128 threads, 8x8 per thread
__global__ __launch_bounds__(128) void k_gemm(const float* __restrict__ x,
                                              const float* __restrict__ W) {
    __shared__ float Ws[DI * DO];    // 32 KB
    __shared__ float xs[16 * 128];   // [k][row], 8 KB
    int t = threadIdx.x;
    int row0 = blockIdx.x * 128;
    // load W
    for (int i = t * 4; i < DI * DO; i += 128 * 4)
        *(float4*)(Ws + i) = *(const float4*)(W + i);

    int cg = t & 7;          // cols cg*8 .. cg*8+7
    int rt = t >> 3;         // rows rt*8 .. rt*8+7
    float acc[8][8];
#pragma unroll
    for (int i = 0; i < 8; i++)
#pragma unroll
        for (int j = 0; j < 8; j++) acc[i][j] = 0.f;

    int grow = row0 + t;     // thread t stages row t of this block
    bool rok = grow < NN;

    for (int kc = 0; kc < 8; kc++) {
        __syncthreads();
        // stage 16 k's of this thread's row, transposed into xs[k][row]
        float4 xa = rok ? *(const float4*)(x + grow * DI + kc * 16 + 0)  : make_float4(0,0,0,0);
        float4 xb = rok ? *(const float4*)(x + grow * DI + kc * 16 + 4)  : make_float4(0,0,0,0);
        float4 xc = rok ? *(const float4*)(x + grow * DI + kc * 16 + 8)  : make_float4(0,0,0,0);
        float4 xd = rok ? *(const float4*)(x + grow * DI + kc * 16 + 12) : make_float4(0,0,0,0);
        xs[0*128+t]=xa.x;  xs[1*128+t]=xa.y;  xs[2*128+t]=xa.z;  xs[3*128+t]=xa.w;
        xs[4*128+t]=xb.x;  xs[5*128+t]=xb.y;  xs[6*128+t]=xb.z;  xs[7*128+t]=xb.w;
        xs[8*128+t]=xc.x;  xs[9*128+t]=xc.y;  xs[10*128+t]=xc.z; xs[11*128+t]=xc.w;
        xs[12*128+t]=xd.x; xs[13*128+t]=xd.y; xs[14*128+t]=xd.z; xs[15*128+t]=xd.w;
        __syncthreads();
#pragma unroll
        for (int k = 0; k < 16; k++) {
            float4 x0 = *(const float4*)(xs + k * 128 + rt * 8);
            float4 x1 = *(const float4*)(xs + k * 128 + rt * 8 + 4);
            float4 w0 = *(const float4*)(Ws + (kc * 16 + k) * DO + cg * 8);
            float4 w1 = *(const float4*)(Ws + (kc * 16 + k) * DO + cg * 8 + 4);
            float xv[8] = {x0.x, x0.y, x0.z, x0.w, x1.x, x1.y, x1.z, x1.w};
            float wv[8] = {w0.x, w0.y, w0.z, w0.w, w1.x, w1.y, w1.z, w1.w};
#pragma unroll
            for (int i = 0; i < 8; i++)
#pragma unroll
                for (int j = 0; j < 8; j++)
                    acc[i][j] += xv[i] * wv[j];
        }
    }
#pragma unroll
    for (int i = 0; i < 8; i++) {
        int gr = row0 + rt * 8 + i;
        if (gr < NN) {
            float4* p = (float4*)(g_h0 + gr * DO + cg * 8);
            p[0] = make_float4(acc[i][0], acc[i][1], acc[i][2], acc[i][3]);
            p[1] = make_float4(acc[i][4], acc[i][5], acc[i][6], acc[i][7]);
        }
    }
}

__global__ __launch_bounds__(256) void k_dinv() {
    int v = blockIdx.x * 256 + threadIdx.x;
    if (v < NN) g_dinv[v] = rsqrtf((float)(g_deg[v] + 1));
}

// acc[dst] += h0[src] * dinv[src]   (16 threads/edge, float4 lanes)
__global__ __launch_bounds__(256) void k_scat1(const int* __restrict__ ei) {
    int t = blockIdx.x * 256 + threadIdx.x;
    int e = t >> 4, q = t & 15;
    if (e >= NE) return;
    int s = ei[e], d = ei[NE + e];
    float ds = g_dinv[s];
    float4 us = *(const float4*)(g_h0 + s * DO + q * 4);
    red_add_v4(g_acc + d * DO + q * 4, us.x * ds, us.y * ds, us.z * ds, us.w * ds);
}

// h = dinv*(acc) + dinv^2*h0 + b ; also nh[v] = ||h_v||^2
__global__ __launch_bounds__(256) void k_h(const float* __restrict__ b) {
    int idx = blockIdx.x * 256 + threadIdx.x;
    if (idx >= NN * DO) return;
    int v = idx >> 6, c = idx & 63;
    float dv = g_dinv[v];
    float h = dv * g_acc[idx] + g_h0[idx] * dv * dv + b[c];
    g_h[idx] = h;
    float p = h * h;
#pragma unroll
    for (int off = 32; off; off >>= 1)
        p += __shfl_down_sync(0xffffffffu, p, off, 64 > 32 ? 32 : 32);
    // 64 elems/node span 2 warps? No: 64 lanes of a node span 2 warps when
    // 256-thread blocks start at node boundaries (idx>>6). Reduce within 32
    // lanes then combine via shared.
    __shared__ float sred[256];
    sred[threadIdx.x] = 0.f;
    __syncthreads();
    // recompute clean 16-lane reduction instead (robust):
    float pp = h * h;
#pragma unroll
    for (int off = 8; off; off >>= 1)
        pp += __shfl_down_sync(0xffffffffu, pp, off, 16);
    if ((threadIdx.x & 15) == 0) sred[threadIdx.x >> 4] = pp;
    __syncthreads();
    // each node = 64 consecutive idx = 4 consecutive 16-lane groups
    if ((threadIdx.x & 63) == 0) {
        int g0 = threadIdx.x >> 4;
        g_nh[v] = sred[g0] + sred[g0 + 1] + sred[g0 + 2] + sred[g0 + 3];
    }
}

// A[dst] += h[src];  e[dst] += ||h_src||^2 (precomputed)
__global__ __launch_bounds__(256) void k_edge2(const int* __restrict__ ei) {
    int t = blockIdx.x * 256 + threadIdx.x;
    int e = t >> 4, q = t & 15;
    if (e >= NE) return;
    int s = ei[e], d = ei[NE + e];
    float4 hs = *(const float4*)(g_h + s * DO + q * 4);
    red_add_v4(g_A + d * DO + q * 4, hs.x, hs.y, hs.z, hs.w);
    if (q == 0) red_add_f32(g_e + d, g_nh[s]);
}

// e[v] = deg_v*nh_v - 2*dot(h_v, A_v) + e[v]   (16 lanes per node)
__global__ __launch_bounds__(256) void k_e() {
    int t = blockIdx.x * 256 + threadIdx.x;
    int v = t >> 4, q = t & 15;
    if (v >= NN) return;
    float4 h4 = *(const float4*)(g_h + v * DO + q * 4);
    float4 a4 = *(const float4*)(g_A + v * DO + q * 4);
    float p = h4.x * a4.x + h4.y * a4.y + h4.z * a4.z + h4.w * a4.w;
#pragma unroll
    for (int off = 8; off; off >>= 1)
        p += __shfl_down_sync(0xffffffffu, p, off, 16);
    if (q == 0)
        g_e[v] = (float)g_deg[v] * g_nh[v] - 2.f * p + g_e[v];
}

__global__ __launch_bounds__(256) void k_max(const float* __restrict__ temp) {
    float tmp = temp[0];
    float m = -1e30f;
    for (int i = blockIdx.x * 256 + threadIdx.x; i < NN; i += gridDim.x * 256)
        m = fmaxf(m, -g_e[i] / tmp);
    __shared__ float sm[256];
    sm[threadIdx.x] = m; __syncthreads();
    for (int o = 128; o; o >>= 1) {
        if (threadIdx.x < o) sm[threadIdx.x] = fmaxf(sm[threadIdx.x], sm[threadIdx.x + o]);
        __syncthreads();
    }
    if (threadIdx.x == 0) g_pmax[blockIdx.x] = sm[0];
}

__global__ __launch_bounds__(256) void k_maxfin() {
    __shared__ float sm[256];
    sm[threadIdx.x] = g_pmax[threadIdx.x];
    __syncthreads();
    for (int o = 128; o; o >>= 1) {
        if (threadIdx.x < o) sm[threadIdx.x] = fmaxf(sm[threadIdx.x], sm[threadIdx.x + o]);
        __syncthreads();
    }
    if (threadIdx.x == 0) g_scal[0] = sm[0];
}

__global__ __launch_bounds__(256) void k_sum(const float* __restrict__ temp) {
    float tmp = temp[0];
    float m = g_scal[0];
    float z = 0.f, w = 0.f;
    for (int i = blockIdx.x * 256 + threadIdx.x; i < NN; i += gridDim.x * 256) {
        float s = -g_e[i] / tmp - m;
        float ez = expf(s);
        z += ez; w += ez * s;
    }
    __shared__ float sz[256], sw[256];
    sz[threadIdx.x] = z; sw[threadIdx.x] = w; __syncthreads();
    for (int o = 128; o; o >>= 1) {
        if (threadIdx.x < o) {
            sz[threadIdx.x] += sz[threadIdx.x + o];
            sw[threadIdx.x] += sw[threadIdx.x + o];
        }
        __syncthreads();
    }
    if (threadIdx.x == 0) { g_pz[blockIdx.x] = sz[0]; g_pw[blockIdx.x] = sw[0]; }
}

__global__ __launch_bounds__(256) void k_sumfin() {
    __shared__ float sz[256], sw[256];
    sz[threadIdx.x] = g_pz[threadIdx.x];
    sw[threadIdx.x] = g_pw[threadIdx.x];
    __syncthreads();
    for (int o = 128; o; o >>= 1) {
        if (threadIdx.x < o) {
            sz[threadIdx.x] += sz[threadIdx.x + o];
            sw[threadIdx.x] += sw[threadIdx.x + o];
        }
        __syncthreads();
    }
    if (threadIdx.x == 0) {
        float Z = sz[0], Wm = sw[0];
        float logZ = logf(Z);
        g_scal[1] = 1.f / Z;
        g_scal[2] = logZ;
        g_scal[3] = logZ - Wm / Z;   // H
    }
}

__global__ __launch_bounds__(256) void k_q(const float* __restrict__ temp) {
    int v = blockIdx.x * 256 + threadIdx.x;
    if (v >= NN) return;
    float tmp = temp[0];
    float s = -g_e[v] / tmp - g_scal[0];        // s - m
    float lp = s - g_scal[2];                   // logp
    g_q[v] = expf(s) * g_scal[1] * (lp + g_scal[3]);
}

// B[src] += q[dst] * h[dst];  Qs[src] += q[dst]
__global__ __launch_bounds__(256) void k_edge3(const int* __restrict__ ei) {
    int t = blockIdx.x * 256 + threadIdx.x;
    int e = t >> 4, q = t & 15;
    if (e >= NE) return;
    int s = ei[e], d = ei[NE + e];
    float qd = g_q[d];
    float4 hd = *(const float4*)(g_h + d * DO + q * 4);
    red_add_v4(g_B + s * DO + q * 4, qd * hd.x, qd * hd.y, qd * hd.z, qd * hd.w);
    if (q == 0) red_add_f32(g_Qs + s, qd);
}

__global__ __launch_bounds__(256) void k_final(const float* __restrict__ wgt,
                                               float* __restrict__ out) {
    int idx = blockIdx.x * 256 + threadIdx.x;
    if (idx >= NN * DO) return;
    int v = idx >> 6;
    float h = g_h[idx];
    float w2 = 2.f * wgt[0];
    float g = g_q[v] * ((float)g_deg[v] * h - g_A[idx]) + g_Qs[v] * h - g_B[idx];
    out[idx] = h + w2 * g;
}

// ---------------- launch ----------------------------------------------------
extern "C" void kernel_launch(void* const* d_in, const int* in_sizes, int n_in,
                              void* d_out, int out_size) {
    const float* x    = (const float*)d_in[0];
    const int*   ei   = (const int*)d_in[1];
    const float* wgt  = (const float*)d_in[2];
    const float* temp = (const float*)d_in[3];
    const float* W    = (const float*)d_in[4];
    const float* b    = (const float*)d_in[5];
    float* out = (float*)d_out;

    const int NB_NODE = (NN * DO + 255) / 256;
    const int NB_E16  = (NE * 16) / 256;
    const int NB_E    = (NE + 255) / 256;
    const int NB_N    = (NN + 255) / 256;
    const int NB_N16  = (NN * 16 + 255) / 256;

    k_zero<<<NB_NODE, 256>>>();
    k_deg<<<NB_E, 256>>>(ei);
    k_gemm<<<(NN + 127) / 128, 128>>>(x, W);
    k_dinv<<<NB_N, 256>>>();
    k_scat1<<<NB_E16, 256>>>(ei);
    k_h<<<NB_NODE, 256>>>(b);
    k_edge2<<<NB_E16, 256>>>(ei);
    k_e<<<NB_N16, 256>>>();
    k_max<<<256, 256>>>(temp);
    k_maxfin<<<1, 256>>>();
    k_sum<<<256, 256>>>(temp);
    k_sumfin<<<1, 256>>>();
    k_q<<<NB_N, 256>>>(temp);
    k_edge3<<<NB_E16, 256>>>(ei);
    k_final<<<NB_NODE, 256>>>(wgt, out);
}

// round 3
// speedup vs baseline: 1.7005x; 1.6321x over previous
#include <cuda_runtime.h>

#define NN 100000
#define NE 1000000
#define DI 128
#define DO 64
#define SB 1024
#define NBLK_SCAN ((NN + SB - 1) / SB)   // 98

// ---------------- scratch (device globals) ----------------------------------
__device__ float g_h0[NN * DO];
__device__ float g_h [NN * DO];
__device__ float g_A [NN * DO];
__device__ int   g_degd[NN];
__device__ int   g_degs[NN];
__device__ int   g_offd[NN + 1];
__device__ int   g_offs[NN + 1];
__device__ int   g_curd[NN];
__device__ int   g_curs[NN];
__device__ int   g_csrd[NE];     // src ids grouped by dst
__device__ int   g_csrs[NE];     // dst ids grouped by src
__device__ int   g_bsumd[NBLK_SCAN + 1];
__device__ int   g_bsums[NBLK_SCAN + 1];
__device__ float g_e[NN];
__device__ float g_nh[NN];
__device__ float g_q[NN];
__device__ float g_dinv[NN];
__device__ float g_pmax[256];
__device__ float g_pz[256];
__device__ float g_pw[256];
__device__ float g_scal[4];   // 0:m  1:1/Z  2:logZ  3:H

// ---------------- CSR build --------------------------------------------------
__global__ __launch_bounds__(256) void k_zero() {
    int i = blockIdx.x * 256 + threadIdx.x;
    if (i < NN) { g_degd[i] = 0; g_degs[i] = 0; }
}

__global__ __launch_bounds__(256) void k_deg(const int* __restrict__ ei) {
    int e = blockIdx.x * 256 + threadIdx.x;
    if (e >= NE) return;
    atomicAdd(&g_degs[ei[e]], 1);
    atomicAdd(&g_degd[ei[NE + e]], 1);
}

// block-local exclusive scans of degd/degs into offd/offs + block totals
__global__ __launch_bounds__(SB) void k_scan1() {
    __shared__ int sd[SB], ss[SB];
    int t = threadIdx.x;
    int i = blockIdx.x * SB + t;
    int a = (i < NN) ? g_degd[i] : 0;
    int b = (i < NN) ? g_degs[i] : 0;
    sd[t] = a; ss[t] = b;
    __syncthreads();
    for (int o = 1; o < SB; o <<= 1) {
        int va = (t >= o) ? sd[t - o] : 0;
        int vb = (t >= o) ? ss[t - o] : 0;
        __syncthreads();
        sd[t] += va; ss[t] += vb;
        __syncthreads();
    }
    if (i < NN) { g_offd[i] = sd[t] - a; g_offs[i] = ss[t] - b; }
    if (t == SB - 1) { g_bsumd[blockIdx.x] = sd[t]; g_bsums[blockIdx.x] = ss[t]; }
}

__global__ __launch_bounds__(128) void k_scan2() {
    __shared__ int sd[128], ss[128];
    int t = threadIdx.x;
    int a = (t < NBLK_SCAN) ? g_bsumd[t] : 0;
    int b = (t < NBLK_SCAN) ? g_bsums[t] : 0;
    sd[t] = a; ss[t] = b;
    __syncthreads();
    for (int o = 1; o < 128; o <<= 1) {
        int va = (t >= o) ? sd[t - o] : 0;
        int vb = (t >= o) ? ss[t - o] : 0;
        __syncthreads();
        sd[t] += va; ss[t] += vb;
        __syncthreads();
    }
    if (t < NBLK_SCAN) { g_bsumd[t] = sd[t] - a; g_bsums[t] = ss[t] - b; }
}

__global__ __launch_bounds__(256) void k_scan3() {
    int i = blockIdx.x * 256 + threadIdx.x;
    if (i < NN) {
        int od = g_offd[i] + g_bsumd[i / SB];
        int os = g_offs[i] + g_bsums[i / SB];
        g_offd[i] = od; g_curd[i] = od;
        g_offs[i] = os; g_curs[i] = os;
        g_dinv[i] = rsqrtf((float)(g_degd[i] + 1));
    }
    if (i == 0) { g_offd[NN] = NE; g_offs[NN] = NE; }
}

__global__ __launch_bounds__(256) void k_fill(const int* __restrict__ ei) {
    int e = blockIdx.x * 256 + threadIdx.x;
    if (e >= NE) return;
    int s = ei[e], d = ei[NE + e];
    int pd = atomicAdd(&g_curd[d], 1);
    g_csrd[pd] = s;
    int ps = atomicAdd(&g_curs[s], 1);
    g_csrs[ps] = d;
}

// ---------------- GEMM: h0 = x @ W (128 rows/block, 8x8 per thread) ----------
__global__ __launch_bounds__(128) void k_gemm(const float* __restrict__ x,
                                              const float* __restrict__ W) {
    __shared__ float Ws[DI * DO];
    __shared__ float xs[16 * 128];
    int t = threadIdx.x;
    int row0 = blockIdx.x * 128;
    for (int i = t * 4; i < DI * DO; i += 128 * 4)
        *(float4*)(Ws + i) = *(const float4*)(W + i);

    int cg = t & 7, rt = t >> 3;
    float acc[8][8];
#pragma unroll
    for (int i = 0; i < 8; i++)
#pragma unroll
        for (int j = 0; j < 8; j++) acc[i][j] = 0.f;

    int grow = row0 + t;
    bool rok = grow < NN;

    for (int kc = 0; kc < 8; kc++) {
        __syncthreads();
        float4 xa = rok ? *(const float4*)(x + grow * DI + kc * 16 + 0)  : make_float4(0,0,0,0);
        float4 xb = rok ? *(const float4*)(x + grow * DI + kc * 16 + 4)  : make_float4(0,0,0,0);
        float4 xc = rok ? *(const float4*)(x + grow * DI + kc * 16 + 8)  : make_float4(0,0,0,0);
        float4 xd = rok ? *(const float4*)(x + grow * DI + kc * 16 + 12) : make_float4(0,0,0,0);
        xs[0*128+t]=xa.x;  xs[1*128+t]=xa.y;  xs[2*128+t]=xa.z;  xs[3*128+t]=xa.w;
        xs[4*128+t]=xb.x;  xs[5*128+t]=xb.y;  xs[6*128+t]=xb.z;  xs[7*128+t]=xb.w;
        xs[8*128+t]=xc.x;  xs[9*128+t]=xc.y;  xs[10*128+t]=xc.z; xs[11*128+t]=xc.w;
        xs[12*128+t]=xd.x; xs[13*128+t]=xd.y; xs[14*128+t]=xd.z; xs[15*128+t]=xd.w;
        __syncthreads();
#pragma unroll
        for (int k = 0; k < 16; k++) {
            float4 x0 = *(const float4*)(xs + k * 128 + rt * 8);
            float4 x1 = *(const float4*)(xs + k * 128 + rt * 8 + 4);
            float4 w0 = *(const float4*)(Ws + (kc * 16 + k) * DO + cg * 8);
            float4 w1 = *(const float4*)(Ws + (kc * 16 + k) * DO + cg * 8 + 4);
            float xv[8] = {x0.x, x0.y, x0.z, x0.w, x1.x, x1.y, x1.z, x1.w};
            float wv[8] = {w0.x, w0.y, w0.z, w0.w, w1.x, w1.y, w1.z, w1.w};
#pragma unroll
            for (int i = 0; i < 8; i++)
#pragma unroll
                for (int j = 0; j < 8; j++)
                    acc[i][j] += xv[i] * wv[j];
        }
    }
#pragma unroll
    for (int i = 0; i < 8; i++) {
        int gr = row0 + rt * 8 + i;
        if (gr < NN) {
            float4* p = (float4*)(g_h0 + gr * DO + cg * 8);
            p[0] = make_float4(acc[i][0], acc[i][1], acc[i][2], acc[i][3]);
            p[1] = make_float4(acc[i][4], acc[i][5], acc[i][6], acc[i][7]);
        }
    }
}

// ---------------- gather passes (16 lanes per node) ---------------------------
// pass1: h_v = dinv_v * sum_{in(v)} h0_s*dinv_s + dinv_v^2*h0_v + b ; nh_v
__global__ __launch_bounds__(256) void k_pass1(const float* __restrict__ b) {
    int t = blockIdx.x * 256 + threadIdx.x;
    int v = t >> 4, q = t & 15;
    if (v >= NN) return;
    int start = g_offd[v], end = g_offd[v + 1];
    float ax = 0.f, ay = 0.f, az = 0.f, aw = 0.f;
    int idx = (start < end) ? g_csrd[start] : 0;
    for (int i = start; i < end; i++) {
        int nidx = (i + 1 < end) ? g_csrd[i + 1] : 0;
        float ds = g_dinv[idx];
        float4 u = *(const float4*)(g_h0 + idx * DO + q * 4);
        ax += u.x * ds; ay += u.y * ds; az += u.z * ds; aw += u.w * ds;
        idx = nidx;
    }
    float dv = g_dinv[v];
    float dv2 = dv * dv;
    float4 h0v = *(const float4*)(g_h0 + v * DO + q * 4);
    float4 bv  = *(const float4*)(b + q * 4);
    float4 h;
    h.x = dv * ax + dv2 * h0v.x + bv.x;
    h.y = dv * ay + dv2 * h0v.y + bv.y;
    h.z = dv * az + dv2 * h0v.z + bv.z;
    h.w = dv * aw + dv2 * h0v.w + bv.w;
    *(float4*)(g_h + v * DO + q * 4) = h;
    float p = h.x * h.x + h.y * h.y + h.z * h.z + h.w * h.w;
#pragma unroll
    for (int off = 8; off; off >>= 1)
        p += __shfl_down_sync(0xffffffffu, p, off, 16);
    if (q == 0) g_nh[v] = p;
}

// pass2: A_v = sum h_s ; e_v = indeg*nh_v - 2*h_v.A_v + sum nh_s
__global__ __launch_bounds__(256) void k_pass2() {
    int t = blockIdx.x * 256 + threadIdx.x;
    int v = t >> 4, q = t & 15;
    if (v >= NN) return;
    int start = g_offd[v], end = g_offd[v + 1];
    float ax = 0.f, ay = 0.f, az = 0.f, aw = 0.f, es = 0.f;
    int idx = (start < end) ? g_csrd[start] : 0;
    for (int i = start; i < end; i++) {
        int nidx = (i + 1 < end) ? g_csrd[i + 1] : 0;
        float4 hs = *(const float4*)(g_h + idx * DO + q * 4);
        ax += hs.x; ay += hs.y; az += hs.z; aw += hs.w;
        if (q == 0) es += g_nh[idx];
        idx = nidx;
    }
    *(float4*)(g_A + v * DO + q * 4) = make_float4(ax, ay, az, aw);
    float4 hv = *(const float4*)(g_h + v * DO + q * 4);
    float p = hv.x * ax + hv.y * ay + hv.z * az + hv.w * aw;
#pragma unroll
    for (int off = 8; off; off >>= 1)
        p += __shfl_down_sync(0xffffffffu, p, off, 16);
    if (q == 0)
        g_e[v] = (float)g_degd[v] * g_nh[v] - 2.f * p + es;
}

// ---------------- softmax scalars ---------------------------------------------
__global__ __launch_bounds__(256) void k_max(const float* __restrict__ temp) {
    float tmp = temp[0];
    float m = -1e30f;
    for (int i = blockIdx.x * 256 + threadIdx.x; i < NN; i += gridDim.x * 256)
        m = fmaxf(m, -g_e[i] / tmp);
    __shared__ float sm[256];
    sm[threadIdx.x] = m; __syncthreads();
    for (int o = 128; o; o >>= 1) {
        if (threadIdx.x < o) sm[threadIdx.x] = fmaxf(sm[threadIdx.x], sm[threadIdx.x + o]);
        __syncthreads();
    }
    if (threadIdx.x == 0) g_pmax[blockIdx.x] = sm[0];
}

__global__ __launch_bounds__(256) void k_maxfin() {
    __shared__ float sm[256];
    sm[threadIdx.x] = g_pmax[threadIdx.x];
    __syncthreads();
    for (int o = 128; o; o >>= 1) {
        if (threadIdx.x < o) sm[threadIdx.x] = fmaxf(sm[threadIdx.x], sm[threadIdx.x + o]);
        __syncthreads();
    }
    if (threadIdx.x == 0) g_scal[0] = sm[0];
}

__global__ __launch_bounds__(256) void k_sum(const float* __restrict__ temp) {
    float tmp = temp[0];
    float m = g_scal[0];
    float z = 0.f, w = 0.f;
    for (int i = blockIdx.x * 256 + threadIdx.x; i < NN; i += gridDim.x * 256) {
        float s = -g_e[i] / tmp - m;
        float ez = expf(s);
        z += ez; w += ez * s;
    }
    __shared__ float sz[256], sw[256];
    sz[threadIdx.x] = z; sw[threadIdx.x] = w; __syncthreads();
    for (int o = 128; o; o >>= 1) {
        if (threadIdx.x < o) {
            sz[threadIdx.x] += sz[threadIdx.x + o];
            sw[threadIdx.x] += sw[threadIdx.x + o];
        }
        __syncthreads();
    }
    if (threadIdx.x == 0) { g_pz[blockIdx.x] = sz[0]; g_pw[blockIdx.x] = sw[0]; }
}

__global__ __launch_bounds__(256) void k_sumfin() {
    __shared__ float sz[256], sw[256];
    sz[threadIdx.x] = g_pz[threadIdx.x];
    sw[threadIdx.x] = g_pw[threadIdx.x];
    __syncthreads();
    for (int o = 128; o; o >>= 1) {
        if (threadIdx.x < o) {
            sz[threadIdx.x] += sz[threadIdx.x + o];
            sw[threadIdx.x] += sw[threadIdx.x + o];
        }
        __syncthreads();
    }
    if (threadIdx.x == 0) {
        float Z = sz[0], Wm = sw[0];
        float logZ = logf(Z);
        g_scal[1] = 1.f / Z;
        g_scal[2] = logZ;
        g_scal[3] = logZ - Wm / Z;   // H
    }
}

__global__ __launch_bounds__(256) void k_q(const float* __restrict__ temp) {
    int v = blockIdx.x * 256 + threadIdx.x;
    if (v >= NN) return;
    float tmp = temp[0];
    float s = -g_e[v] / tmp - g_scal[0];
    float lp = s - g_scal[2];
    g_q[v] = expf(s) * g_scal[1] * (lp + g_scal[3]);
}

// pass3 + final: B_v = sum q_d h_d; Qs_v = sum q_d (over out-edges); write out
__global__ __launch_bounds__(256) void k_pass3(const float* __restrict__ wgt,
                                               float* __restrict__ out) {
    int t = blockIdx.x * 256 + threadIdx.x;
    int v = t >> 4, q = t & 15;
    if (v >= NN) return;
    int start = g_offs[v], end = g_offs[v + 1];
    float bx = 0.f, by = 0.f, bz = 0.f, bw = 0.f, Qs = 0.f;
    int idx = (start < end) ? g_csrs[start] : 0;
    for (int i = start; i < end; i++) {
        int nidx = (i + 1 < end) ? g_csrs[i + 1] : 0;
        float qd = g_q[idx];
        float4 hd = *(const float4*)(g_h + idx * DO + q * 4);
        bx += qd * hd.x; by += qd * hd.y; bz += qd * hd.z; bw += qd * hd.w;
        Qs += qd;
        idx = nidx;
    }
    float4 hv = *(const float4*)(g_h + v * DO + q * 4);
    float4 Av = *(const float4*)(g_A + v * DO + q * 4);
    float qv = g_q[v];
    float dg = (float)g_degd[v];
    float w2 = 2.f * wgt[0];
    float4 o;
    o.x = hv.x + w2 * (qv * (dg * hv.x - Av.x) + Qs * hv.x - bx);
    o.y = hv.y + w2 * (qv * (dg * hv.y - Av.y) + Qs * hv.y - by);
    o.z = hv.z + w2 * (qv * (dg * hv.z - Av.z) + Qs * hv.z - bz);
    o.w = hv.w + w2 * (qv * (dg * hv.w - Av.w) + Qs * hv.w - bw);
    *(float4*)(out + v * DO + q * 4) = o;
}

// ---------------- launch ----------------------------------------------------
extern "C" void kernel_launch(void* const* d_in, const int* in_sizes, int n_in,
                              void* d_out, int out_size) {
    const float* x    = (const float*)d_in[0];
    const int*   ei   = (const int*)d_in[1];
    const float* wgt  = (const float*)d_in[2];
    const float* temp = (const float*)d_in[3];
    const float* W    = (const float*)d_in[4];
    const float* b    = (const float*)d_in[5];
    float* out = (float*)d_out;

    const int NB_E   = (NE + 255) / 256;
    const int NB_N   = (NN + 255) / 256;
    const int NB_N16 = (NN * 16 + 255) / 256;

    k_zero<<<NB_N, 256>>>();
    k_deg<<<NB_E, 256>>>(ei);
    k_scan1<<<NBLK_SCAN, SB>>>();
    k_scan2<<<1, 128>>>();
    k_scan3<<<NB_N, 256>>>();
    k_fill<<<NB_E, 256>>>(ei);
    k_gemm<<<(NN + 127) / 128, 128>>>(x, W);
    k_pass1<<<NB_N16, 256>>>(b);
    k_pass2<<<NB_N16, 256>>>();
    k_max<<<256, 256>>>(temp);
    k_maxfin<<<1, 256>>>();
    k_sum<<<256, 256>>>(temp);
    k_sumfin<<<1, 256>>>();
    k_q<<<NB_N, 256>>>(temp);
    k_pass3<<<NB_N16, 256>>>(wgt, out);
}